// round 1
// baseline (speedup 1.0000x reference)
#include <cuda_runtime.h>
#include <math.h>

#define BATCH 2048
#define NTOK 98
#define DIM 128
#define HEADS 4
#define HD 32
#define NWIN 256
#define NN (NTOK * NTOK)   // 9604

// Scratch (device-global; no runtime allocation allowed)
__device__ float g_qkv[(size_t)BATCH * NTOK * 3 * DIM];   // [b][n][s*128 + h*32 + d]
__device__ float g_att[(size_t)BATCH * NTOK * DIM];       // [b][n][h*32 + d]
__device__ float g_bias[HEADS * NN];                      // [h][n][m]

// ---------------------------------------------------------------------------
// Bias gather: g_bias[h][n][m] = bias_table[rel_index[n][m]][h]
// ---------------------------------------------------------------------------
__global__ void build_bias_kernel(const float* __restrict__ table,
                                  const int* __restrict__ rel) {
    int idx = blockIdx.x * blockDim.x + threadIdx.x;
    if (idx < HEADS * NN) {
        int h = idx / NN;
        int nm = idx - h * NN;
        g_bias[idx] = table[rel[nm] * HEADS + h];
    }
}

// ---------------------------------------------------------------------------
// GEMM: C[M][N] = A[M][128] * W[N][128]^T + bias[N]
// Block tile 64(M) x 128(N), K=128 resident in smem. 256 threads, 4x8 per
// thread via strided mapping (m = ty+16i, n = tx+16j).
//   As row-major [64][128]  -> a-frag reads are warp broadcasts
//   Ws transposed [128][129] (pad) -> w-frag reads conflict-free
// ---------------------------------------------------------------------------
#define GEMM_SMEM ((64 * 128 + 128 * 129) * 4)

__global__ __launch_bounds__(256, 2) void gemm128_kernel(
    const float* __restrict__ A, const float* __restrict__ W,
    const float* __restrict__ bias, float* __restrict__ C, int N)
{
    extern __shared__ float sm[];
    float* As = sm;              // [64][128]
    float* Ws = sm + 64 * 128;   // [128][129]

    int tid = threadIdx.x;
    size_t m0 = (size_t)blockIdx.x * 64;
    int n0 = blockIdx.y * 128;

    // Load A tile (contiguous 64x128 block)
    const float4* Ag = (const float4*)(A + m0 * 128);
    float4* As4 = (float4*)As;
#pragma unroll
    for (int it = 0; it < 8; it++)
        As4[tid + 256 * it] = Ag[tid + 256 * it];

    // Load W tile, store transposed with pad (conflict-free scatter)
    const float4* Wg = (const float4*)(W + (size_t)n0 * 128);
#pragma unroll
    for (int it = 0; it < 16; it++) {
        int idx = tid + 256 * it;
        int n = idx >> 5;            // 0..127
        int k4 = (idx & 31) << 2;    // 0..124
        float4 v = Wg[idx];
        Ws[(k4 + 0) * 129 + n] = v.x;
        Ws[(k4 + 1) * 129 + n] = v.y;
        Ws[(k4 + 2) * 129 + n] = v.z;
        Ws[(k4 + 3) * 129 + n] = v.w;
    }
    __syncthreads();

    int tx = tid & 15, ty = tid >> 4;
    float acc[4][8];
#pragma unroll
    for (int i = 0; i < 4; i++)
#pragma unroll
        for (int j = 0; j < 8; j++) acc[i][j] = 0.f;

#pragma unroll 8
    for (int kk = 0; kk < 128; kk++) {
        float a[4], w[8];
#pragma unroll
        for (int i = 0; i < 4; i++) a[i] = As[(ty + 16 * i) * 128 + kk];
#pragma unroll
        for (int j = 0; j < 8; j++) w[j] = Ws[kk * 129 + tx + 16 * j];
#pragma unroll
        for (int i = 0; i < 4; i++)
#pragma unroll
            for (int j = 0; j < 8; j++) acc[i][j] += a[i] * w[j];
    }

#pragma unroll
    for (int j = 0; j < 8; j++) {
        float bv = bias[n0 + tx + 16 * j];
#pragma unroll
        for (int i = 0; i < 4; i++) {
            C[(m0 + ty + 16 * i) * (size_t)N + n0 + tx + 16 * j] = acc[i][j] + bv;
        }
    }
}

// ---------------------------------------------------------------------------
// Attention: one block per (window b, head h).
//   q,k,v loaded from g_qkv; QK^T (7x7 reg tile per thread over 112x112),
//   + bias + mask, row softmax, PV, write to g_att.
// ---------------------------------------------------------------------------
#define SA 113
#define ATTN_SMEM ((112 * 32 + 32 * SA + 98 * 32 + 112 * SA) * 4)

__global__ __launch_bounds__(256, 2) void attn_kernel(const float* __restrict__ mask) {
    extern __shared__ float sm[];
    float* qs  = sm;                 // [112][32] (rows >=98 unused garbage)
    float* kst = qs + 112 * 32;      // [32][113] transposed k
    float* vs  = kst + 32 * SA;      // [98][32]
    float* att = vs + 98 * 32;       // [112][113] (rows >=98 garbage, guarded)

    int b = blockIdx.x, h = blockIdx.y;
    int tid = threadIdx.x;
    const float scale = 0.17677669529663687f;  // 32^-0.5

    const float* qg = g_qkv + (size_t)b * NTOK * 384 + h * 32;
    const float* kg = qg + 128;
    const float* vg = qg + 256;

    // Fill q (scaled), v (row-major), k (transposed)
    for (int idx = tid; idx < NTOK * 8; idx += 256) {
        int n = idx >> 3;
        int c = (idx & 7) << 2;
        float4 vq = *(const float4*)(qg + (size_t)n * 384 + c);
        qs[n * 32 + c + 0] = vq.x * scale;
        qs[n * 32 + c + 1] = vq.y * scale;
        qs[n * 32 + c + 2] = vq.z * scale;
        qs[n * 32 + c + 3] = vq.w * scale;
        float4 vv = *(const float4*)(vg + (size_t)n * 384 + c);
        *(float4*)(vs + n * 32 + c) = vv;
        float4 vk = *(const float4*)(kg + (size_t)n * 384 + c);
        kst[(c + 0) * SA + n] = vk.x;
        kst[(c + 1) * SA + n] = vk.y;
        kst[(c + 2) * SA + n] = vk.z;
        kst[(c + 3) * SA + n] = vk.w;
    }
    __syncthreads();

    int tx = tid & 15, ty = tid >> 4;

    // QK^T
    float acc[7][7];
#pragma unroll
    for (int i = 0; i < 7; i++)
#pragma unroll
        for (int j = 0; j < 7; j++) acc[i][j] = 0.f;

#pragma unroll 4
    for (int kk = 0; kk < 32; kk++) {
        float a[7], w[7];
#pragma unroll
        for (int i = 0; i < 7; i++) a[i] = qs[(ty + 16 * i) * 32 + kk];
#pragma unroll
        for (int j = 0; j < 7; j++) w[j] = kst[kk * SA + tx + 16 * j];
#pragma unroll
        for (int i = 0; i < 7; i++)
#pragma unroll
            for (int j = 0; j < 7; j++) acc[i][j] += a[i] * w[j];
    }

    const float* mrow = mask + (size_t)(b & (NWIN - 1)) * NN;
    const float* brow = g_bias + h * NN;
#pragma unroll
    for (int i = 0; i < 7; i++) {
        int n = ty + 16 * i;
        if (n < NTOK) {
#pragma unroll
            for (int j = 0; j < 7; j++) {
                int m = tx + 16 * j;
                if (m < NTOK)
                    att[n * SA + m] = acc[i][j] + brow[n * NTOK + m] + mrow[n * NTOK + m];
            }
        }
    }
    __syncthreads();

    // Row softmax (warp per row, 8 rows round-robin)
    int warp = tid >> 5, lane = tid & 31;
    for (int n = warp; n < NTOK; n += 8) {
        float* row = att + n * SA;
        float vals[4];
        float mx = -1e30f;
#pragma unroll
        for (int k = 0; k < 4; k++) {
            int m = lane + 32 * k;
            vals[k] = (m < NTOK) ? row[m] : -1e30f;
            mx = fmaxf(mx, vals[k]);
        }
#pragma unroll
        for (int off = 16; off > 0; off >>= 1)
            mx = fmaxf(mx, __shfl_xor_sync(0xffffffffu, mx, off));
        float s = 0.f;
#pragma unroll
        for (int k = 0; k < 4; k++) {
            int m = lane + 32 * k;
            if (m < NTOK) {
                float e = __expf(vals[k] - mx);
                row[m] = e;
                s += e;
            }
        }
#pragma unroll
        for (int off = 16; off > 0; off >>= 1)
            s += __shfl_xor_sync(0xffffffffu, s, off);
        float inv = 1.f / s;
#pragma unroll
        for (int k = 0; k < 4; k++) {
            int m = lane + 32 * k;
            if (m < NTOK) row[m] *= inv;
        }
    }
    __syncthreads();

    // PV: out[n][d] = sum_m att[n][m] * v[m][d]
    float oacc[7][2];
#pragma unroll
    for (int i = 0; i < 7; i++) { oacc[i][0] = 0.f; oacc[i][1] = 0.f; }

#pragma unroll 2
    for (int m = 0; m < NTOK; m++) {
        float aa[7];
#pragma unroll
        for (int i = 0; i < 7; i++) aa[i] = att[(ty + 16 * i) * SA + m];
        float v0 = vs[m * 32 + tx];
        float v1 = vs[m * 32 + tx + 16];
#pragma unroll
        for (int i = 0; i < 7; i++) {
            oacc[i][0] += aa[i] * v0;
            oacc[i][1] += aa[i] * v1;
        }
    }

    float* og = g_att + (size_t)b * NTOK * 128 + h * 32;
#pragma unroll
    for (int i = 0; i < 7; i++) {
        int n = ty + 16 * i;
        if (n < NTOK) {
            og[(size_t)n * 128 + tx] = oacc[i][0];
            og[(size_t)n * 128 + tx + 16] = oacc[i][1];
        }
    }
}

// ---------------------------------------------------------------------------
extern "C" void kernel_launch(void* const* d_in, const int* in_sizes, int n_in,
                              void* d_out, int out_size) {
    const float* x          = (const float*)d_in[0];
    const float* mask       = (const float*)d_in[1];
    const float* qkv_w      = (const float*)d_in[2];
    const float* qkv_b      = (const float*)d_in[3];
    const float* proj_w     = (const float*)d_in[4];
    const float* proj_b     = (const float*)d_in[5];
    const float* bias_table = (const float*)d_in[6];
    const int*   rel_index  = (const int*)d_in[7];
    float* out = (float*)d_out;

    float *qkv_ptr, *att_ptr;
    cudaGetSymbolAddress((void**)&qkv_ptr, g_qkv);
    cudaGetSymbolAddress((void**)&att_ptr, g_att);

    cudaFuncSetAttribute(gemm128_kernel,
                         cudaFuncAttributeMaxDynamicSharedMemorySize, GEMM_SMEM);
    cudaFuncSetAttribute(attn_kernel,
                         cudaFuncAttributeMaxDynamicSharedMemorySize, ATTN_SMEM);

    // 1. bias gather
    build_bias_kernel<<<(HEADS * NN + 255) / 256, 256>>>(bias_table, rel_index);
    // 2. QKV projection: (200704 x 128) @ (128 x 384)
    gemm128_kernel<<<dim3(BATCH * NTOK / 64, 3), 256, GEMM_SMEM>>>(
        x, qkv_w, qkv_b, qkv_ptr, 3 * DIM);
    // 3. attention per (window, head)
    attn_kernel<<<dim3(BATCH, HEADS), 256, ATTN_SMEM>>>(mask);
    // 4. output projection: (200704 x 128) @ (128 x 128)
    gemm128_kernel<<<dim3(BATCH * NTOK / 64, 1), 256, GEMM_SMEM>>>(
        att_ptr, proj_w, proj_b, out, DIM);
}

// round 3
// speedup vs baseline: 1.2412x; 1.2412x over previous
#include <cuda_runtime.h>
#include <cuda_bf16.h>
#include <stdint.h>
#include <math.h>

#define BATCH 2048
#define NTOK 98
#define DIM 128
#define HEADS 4
#define NWIN 256
#define NN (NTOK * NTOK)   // 9604

// Scratch (device globals; no runtime allocation allowed)
__device__ float g_qkv[(size_t)BATCH * NTOK * 3 * DIM];     // [b][n][s*128+h*32+d]
__device__ float g_att[(size_t)BATCH * NTOK * DIM];         // [b][n][h*32+d]
__device__ __nv_bfloat16 g_sbm[(size_t)NWIN * HEADS * NN];  // bias+mask, bf16

// ===========================================================================
__device__ __forceinline__ uint32_t smem_u32(const void* p) {
    uint32_t a;
    asm("{ .reg .u64 t; cvta.to.shared.u64 t, %1; cvt.u32.u64 %0, t; }" : "=r"(a) : "l"(p));
    return a;
}
__device__ __forceinline__ void ldsm_x4(uint32_t* r, uint32_t addr) {
    asm volatile("ldmatrix.sync.aligned.m8n8.x4.shared.b16 {%0,%1,%2,%3}, [%4];"
                 : "=r"(r[0]), "=r"(r[1]), "=r"(r[2]), "=r"(r[3]) : "r"(addr));
}
__device__ __forceinline__ void ldsm_x2(uint32_t* r, uint32_t addr) {
    asm volatile("ldmatrix.sync.aligned.m8n8.x2.shared.b16 {%0,%1}, [%2];"
                 : "=r"(r[0]), "=r"(r[1]) : "r"(addr));
}
__device__ __forceinline__ void ldsm_x2t(uint32_t* r, uint32_t addr) {
    asm volatile("ldmatrix.sync.aligned.m8n8.x2.trans.shared.b16 {%0,%1}, [%2];"
                 : "=r"(r[0]), "=r"(r[1]) : "r"(addr));
}
__device__ __forceinline__ void mma_bf16(float* d, const uint32_t* a, const uint32_t* b) {
    asm volatile("mma.sync.aligned.m16n8k16.row.col.f32.bf16.bf16.f32 "
                 "{%0,%1,%2,%3}, {%4,%5,%6,%7}, {%8,%9}, {%0,%1,%2,%3};"
                 : "+f"(d[0]), "+f"(d[1]), "+f"(d[2]), "+f"(d[3])
                 : "r"(a[0]), "r"(a[1]), "r"(a[2]), "r"(a[3]), "r"(b[0]), "r"(b[1]));
}
__device__ __forceinline__ uint32_t packbf(float a, float b) {
    __nv_bfloat162 t = __float22bfloat162_rn(make_float2(a, b));
    return *(uint32_t*)&t;
}
__device__ __forceinline__ float lopart(float v) {
    return v - __bfloat162float(__float2bfloat16(v));
}
__device__ __forceinline__ void split4(float4 v, uint2& hi, uint2& lo) {
    __nv_bfloat16 hx = __float2bfloat16(v.x), hy = __float2bfloat16(v.y);
    __nv_bfloat16 hz = __float2bfloat16(v.z), hw = __float2bfloat16(v.w);
    __nv_bfloat162 h0 = __halves2bfloat162(hx, hy), h1 = __halves2bfloat162(hz, hw);
    hi.x = *(uint32_t*)&h0; hi.y = *(uint32_t*)&h1;
    lo.x = packbf(v.x - __bfloat162float(hx), v.y - __bfloat162float(hy));
    lo.y = packbf(v.z - __bfloat162float(hz), v.w - __bfloat162float(hw));
}

// ===========================================================================
// bias+mask combine: g_sbm[w][h][n][m] = bf16(table[rel[nm]][h] + mask[w][nm])
// ===========================================================================
__global__ void build_sbm_kernel(const float* __restrict__ table,
                                 const int* __restrict__ rel,
                                 const float* __restrict__ mask) {
    int nm = blockIdx.x * 256 + threadIdx.x;
    int wh = blockIdx.y;
    if (nm < NN) {
        int w = wh >> 2, h = wh & 3;
        float v = table[rel[nm] * HEADS + h] + mask[(size_t)w * NN + nm];
        g_sbm[(size_t)wh * NN + nm] = __float2bfloat16(v);
    }
}

// ===========================================================================
// fp32 SGEMM (projections)
// ===========================================================================
#define GEMM_SMEM ((64 * 128 + 128 * 129) * 4)

__global__ __launch_bounds__(256, 2) void gemm128_kernel(
    const float* __restrict__ A, const float* __restrict__ W,
    const float* __restrict__ bias, float* __restrict__ C, int N)
{
    extern __shared__ float smf[];
    float* As = smf;
    float* Ws = smf + 64 * 128;

    int tid = threadIdx.x;
    size_t m0 = (size_t)blockIdx.x * 64;
    int n0 = blockIdx.y * 128;

    const float4* Ag = (const float4*)(A + m0 * 128);
    float4* As4 = (float4*)As;
#pragma unroll
    for (int it = 0; it < 8; it++) As4[tid + 256 * it] = Ag[tid + 256 * it];

    const float4* Wg = (const float4*)(W + (size_t)n0 * 128);
#pragma unroll
    for (int it = 0; it < 16; it++) {
        int idx = tid + 256 * it;
        int n = idx >> 5;
        int k4 = (idx & 31) << 2;
        float4 v = Wg[idx];
        Ws[(k4 + 0) * 129 + n] = v.x;
        Ws[(k4 + 1) * 129 + n] = v.y;
        Ws[(k4 + 2) * 129 + n] = v.z;
        Ws[(k4 + 3) * 129 + n] = v.w;
    }
    __syncthreads();

    int tx = tid & 15, ty = tid >> 4;
    float acc[4][8];
#pragma unroll
    for (int i = 0; i < 4; i++)
#pragma unroll
        for (int j = 0; j < 8; j++) acc[i][j] = 0.f;

#pragma unroll 8
    for (int kk = 0; kk < 128; kk++) {
        float a[4], w[8];
#pragma unroll
        for (int i = 0; i < 4; i++) a[i] = As[(ty + 16 * i) * 128 + kk];
#pragma unroll
        for (int j = 0; j < 8; j++) w[j] = Ws[kk * 129 + tx + 16 * j];
#pragma unroll
        for (int i = 0; i < 4; i++)
#pragma unroll
            for (int j = 0; j < 8; j++) acc[i][j] += a[i] * w[j];
    }

#pragma unroll
    for (int j = 0; j < 8; j++) {
        float bv = bias[n0 + tx + 16 * j];
#pragma unroll
        for (int i = 0; i < 4; i++)
            C[(m0 + ty + 16 * i) * (size_t)N + n0 + tx + 16 * j] = acc[i][j] + bv;
    }
}

// ===========================================================================
// HMMA attention: one CTA per (window, head), 128 threads (4 warps).
// Warp w owns output rows [32w, 32w+32). S kept in C-fragments; softmax via
// quad shuffles; P re-packed into A-fragments for PV. bf16 hi/lo x3 split.
// ===========================================================================
#define PITCH 80            // bytes per smem tile row (40 bf16)
#define QH_OFF 0            // 128 rows
#define QL_OFF 10240
#define KH_OFF 20480        // 112 rows
#define KL_OFF 29440
#define VH_OFF 38400        // 112 rows
#define VL_OFF 47360
#define SB_OFF 56320        // 98*196 = 19208 B
#define ATTN_SMEM 75584

__global__ __launch_bounds__(128) void attn_hmma_kernel() {
    extern __shared__ char smraw[];
    const uint32_t smb = smem_u32(smraw);
    char* sm = smraw;

    const int b = blockIdx.x, h = blockIdx.y;
    const int tid = threadIdx.x;
    const int wid = tid >> 5, lane = tid & 31;

    // ---- zero operand tiles (pads must be exactly 0) ----
    {
        float4 z = make_float4(0.f, 0.f, 0.f, 0.f);
        float4* p = (float4*)sm;
#pragma unroll
        for (int i = 0; i < 28; i++) {
            int idx = tid + 128 * i;
            if (idx < 3520) p[idx] = z;   // 3520*16 = 56320
        }
    }
    __syncthreads();

    // ---- load Q (scaled) / K / V, split hi/lo bf16, pitch-80 rows ----
    const float scale = 0.17677669529663687f;
    const float* qg = g_qkv + ((size_t)b * NTOK) * 384 + h * 32;
    for (int idx = tid; idx < NTOK * 8; idx += 128) {
        int n = idx >> 3, c4 = (idx & 7) << 2;
        const float* src = qg + (size_t)n * 384 + c4;
        uint32_t off = (uint32_t)(n * PITCH + c4 * 2);
        uint2 hi, lo;

        float4 q = *(const float4*)src;
        q.x *= scale; q.y *= scale; q.z *= scale; q.w *= scale;
        split4(q, hi, lo);
        *(uint2*)(sm + QH_OFF + off) = hi;
        *(uint2*)(sm + QL_OFF + off) = lo;

        split4(*(const float4*)(src + 128), hi, lo);
        *(uint2*)(sm + KH_OFF + off) = hi;
        *(uint2*)(sm + KL_OFF + off) = lo;

        split4(*(const float4*)(src + 256), hi, lo);
        *(uint2*)(sm + VH_OFF + off) = hi;
        *(uint2*)(sm + VL_OFF + off) = lo;
    }
    // stage bias+mask tile (contiguous 19208 B)
    {
        const uint32_t* src = (const uint32_t*)(g_sbm + ((size_t)((b & (NWIN - 1)) * HEADS + h)) * NN);
        uint32_t* dst = (uint32_t*)(sm + SB_OFF);
        for (int i = tid; i < NN / 2; i += 128) dst[i] = src[i];
    }
    __syncthreads();

    const int l8 = lane & 7;
    const int rq = lane >> 2;         // row within 8
    const int cq = (lane & 3) * 2;    // col pair base

    // ---- S = QK^T via 3 bf16 passes, C-frags: acc[mi][nt][4] ----
    float acc[2][13][4];
#pragma unroll
    for (int mi = 0; mi < 2; mi++)
#pragma unroll
        for (int nt = 0; nt < 13; nt++)
#pragma unroll
            for (int c = 0; c < 4; c++) acc[mi][nt][c] = 0.f;

    uint32_t qbase[3] = {smb + QH_OFF, smb + QH_OFF, smb + QL_OFF};
    uint32_t kbase[3] = {smb + KH_OFF, smb + KL_OFF, smb + KH_OFF};

#pragma unroll 1
    for (int p = 0; p < 3; p++) {
        uint32_t qb = qbase[p], kb = kbase[p];
#pragma unroll
        for (int kc = 0; kc < 2; kc++) {
            int sel = lane >> 3;
            uint32_t arow = (uint32_t)(wid * 32 + (sel & 1) * 8 + l8);
            uint32_t aoff = (uint32_t)(kc * 32 + (sel >> 1) * 16);
            uint32_t a0[4], a1[4];
            ldsm_x4(a0, qb + arow * PITCH + aoff);
            ldsm_x4(a1, qb + (arow + 16) * PITCH + aoff);
            uint32_t boff = (uint32_t)(kc * 32 + ((lane >> 3) & 1) * 16);
#pragma unroll
            for (int nt = 0; nt < 13; nt++) {
                uint32_t bf[2];
                ldsm_x2(bf, kb + (uint32_t)(nt * 8 + l8) * PITCH + boff);
                mma_bf16(acc[0][nt], a0, bf);
                mma_bf16(acc[1][nt], a1, bf);
            }
        }
    }

    // ---- bias+mask add, masking of pad cols, softmax (quad shuffles) ----
    float sumA[2], sumB[2];
#pragma unroll
    for (int mi = 0; mi < 2; mi++) {
        int rA = wid * 32 + mi * 16 + rq;
        int rB = rA + 8;
        float mxA = -1e30f, mxB = -1e30f;
#pragma unroll
        for (int nt = 0; nt < 13; nt++) {
            int col = nt * 8 + cq;
            if (col < 98) {
                if (rA < 98) {
                    uint32_t u = *(const uint32_t*)(sm + SB_OFF + rA * 196 + col * 2);
                    __nv_bfloat162 bb = *(__nv_bfloat162*)&u;
                    acc[mi][nt][0] += __bfloat162float(bb.x);
                    acc[mi][nt][1] += __bfloat162float(bb.y);
                }
                if (rB < 98) {
                    uint32_t u = *(const uint32_t*)(sm + SB_OFF + rB * 196 + col * 2);
                    __nv_bfloat162 bb = *(__nv_bfloat162*)&u;
                    acc[mi][nt][2] += __bfloat162float(bb.x);
                    acc[mi][nt][3] += __bfloat162float(bb.y);
                }
            } else {
                acc[mi][nt][0] = -1e30f; acc[mi][nt][1] = -1e30f;
                acc[mi][nt][2] = -1e30f; acc[mi][nt][3] = -1e30f;
            }
            mxA = fmaxf(mxA, fmaxf(acc[mi][nt][0], acc[mi][nt][1]));
            mxB = fmaxf(mxB, fmaxf(acc[mi][nt][2], acc[mi][nt][3]));
        }
        mxA = fmaxf(mxA, __shfl_xor_sync(0xffffffffu, mxA, 1));
        mxA = fmaxf(mxA, __shfl_xor_sync(0xffffffffu, mxA, 2));
        mxB = fmaxf(mxB, __shfl_xor_sync(0xffffffffu, mxB, 1));
        mxB = fmaxf(mxB, __shfl_xor_sync(0xffffffffu, mxB, 2));
        float sA = 0.f, sB = 0.f;
#pragma unroll
        for (int nt = 0; nt < 13; nt++) {
            float e0 = __expf(acc[mi][nt][0] - mxA);
            float e1 = __expf(acc[mi][nt][1] - mxA);
            float e2 = __expf(acc[mi][nt][2] - mxB);
            float e3 = __expf(acc[mi][nt][3] - mxB);
            acc[mi][nt][0] = e0; acc[mi][nt][1] = e1;
            acc[mi][nt][2] = e2; acc[mi][nt][3] = e3;
            sA += e0 + e1; sB += e2 + e3;
        }
        sA += __shfl_xor_sync(0xffffffffu, sA, 1);
        sA += __shfl_xor_sync(0xffffffffu, sA, 2);
        sB += __shfl_xor_sync(0xffffffffu, sB, 1);
        sB += __shfl_xor_sync(0xffffffffu, sB, 2);
        sumA[mi] = sA; sumB[mi] = sB;
    }

    // ---- O = P V via 3 bf16 passes (Phi*Vhi + Phi*Vlo + Plo*Vhi) ----
    float oacc[2][4][4];
#pragma unroll
    for (int mi = 0; mi < 2; mi++)
#pragma unroll
        for (int nh = 0; nh < 4; nh++)
#pragma unroll
            for (int c = 0; c < 4; c++) oacc[mi][nh][c] = 0.f;

    uint32_t vbase[3] = {smb + VH_OFF, smb + VL_OFF, smb + VH_OFF};

#pragma unroll 1
    for (int p = 0; p < 3; p++) {
        uint32_t vb = vbase[p];
        bool lo = (p == 2);
#pragma unroll
        for (int kc = 0; kc < 7; kc++) {
            uint32_t amat[2][4];
#pragma unroll
            for (int mi = 0; mi < 2; mi++) {
                int nt0 = 2 * kc, nt1 = nt0 + 1;
                float v0 = acc[mi][nt0][0], v1 = acc[mi][nt0][1];
                float v2 = acc[mi][nt0][2], v3 = acc[mi][nt0][3];
                float w0 = 0.f, w1 = 0.f, w2 = 0.f, w3 = 0.f;
                if (nt1 < 13) {
                    w0 = acc[mi][nt1][0]; w1 = acc[mi][nt1][1];
                    w2 = acc[mi][nt1][2]; w3 = acc[mi][nt1][3];
                }
                if (lo) {
                    v0 = lopart(v0); v1 = lopart(v1); v2 = lopart(v2); v3 = lopart(v3);
                    w0 = lopart(w0); w1 = lopart(w1); w2 = lopart(w2); w3 = lopart(w3);
                }
                amat[mi][0] = packbf(v0, v1);
                amat[mi][1] = packbf(v2, v3);
                amat[mi][2] = packbf(w0, w1);
                amat[mi][3] = packbf(w2, w3);
            }
            uint32_t vrow = (uint32_t)(kc * 16 + ((lane >> 3) & 1) * 8 + l8);
#pragma unroll
            for (int nh = 0; nh < 4; nh++) {
                uint32_t bf[2];
                ldsm_x2t(bf, vb + vrow * PITCH + nh * 16);
                mma_bf16(oacc[0][nh], amat[0], bf);
                mma_bf16(oacc[1][nh], amat[1], bf);
            }
        }
    }

    // ---- epilogue: scale by 1/rowsum, write rows < 98 ----
#pragma unroll
    for (int mi = 0; mi < 2; mi++) {
        int rA = wid * 32 + mi * 16 + rq;
        int rB = rA + 8;
        float invA = 1.0f / sumA[mi];
        float invB = 1.0f / sumB[mi];
#pragma unroll
        for (int nh = 0; nh < 4; nh++) {
            int col = nh * 8 + cq;
            if (rA < 98) {
                float2 o = make_float2(oacc[mi][nh][0] * invA, oacc[mi][nh][1] * invA);
                *(float2*)(g_att + ((size_t)b * NTOK + rA) * 128 + h * 32 + col) = o;
            }
            if (rB < 98) {
                float2 o = make_float2(oacc[mi][nh][2] * invB, oacc[mi][nh][3] * invB);
                *(float2*)(g_att + ((size_t)b * NTOK + rB) * 128 + h * 32 + col) = o;
            }
        }
    }
}

// ===========================================================================
extern "C" void kernel_launch(void* const* d_in, const int* in_sizes, int n_in,
                              void* d_out, int out_size) {
    const float* x          = (const float*)d_in[0];
    const float* mask       = (const float*)d_in[1];
    const float* qkv_w      = (const float*)d_in[2];
    const float* qkv_b      = (const float*)d_in[3];
    const float* proj_w     = (const float*)d_in[4];
    const float* proj_b     = (const float*)d_in[5];
    const float* bias_table = (const float*)d_in[6];
    const int*   rel_index  = (const int*)d_in[7];
    float* out = (float*)d_out;

    float *qkv_ptr, *att_ptr;
    cudaGetSymbolAddress((void**)&qkv_ptr, g_qkv);
    cudaGetSymbolAddress((void**)&att_ptr, g_att);

    cudaFuncSetAttribute(gemm128_kernel,
                         cudaFuncAttributeMaxDynamicSharedMemorySize, GEMM_SMEM);
    cudaFuncSetAttribute(attn_hmma_kernel,
                         cudaFuncAttributeMaxDynamicSharedMemorySize, ATTN_SMEM);

    build_sbm_kernel<<<dim3((NN + 255) / 256, NWIN * HEADS), 256>>>(bias_table, rel_index, mask);
    gemm128_kernel<<<dim3(BATCH * NTOK / 64, 3), 256, GEMM_SMEM>>>(
        x, qkv_w, qkv_b, qkv_ptr, 3 * DIM);
    attn_hmma_kernel<<<dim3(BATCH, HEADS), 128, ATTN_SMEM>>>();
    gemm128_kernel<<<dim3(BATCH * NTOK / 64, 1), 256, GEMM_SMEM>>>(
        att_ptr, proj_w, proj_b, out, DIM);
}